// round 2
// baseline (speedup 1.0000x reference)
#include <cuda_runtime.h>
#include <cstdint>

// Problem constants
#define Bn 16
#define Cn 256
#define Hn 128
#define Wn 128
#define HW (Hn*Wn)            // 16384 = 2^14
#define CHW (Cn*HW)           // 4194304 = 2^22
#define BHW (Bn*HW)           // 262144
#define TOTAL (Bn*CHW)        // 67108864

// Scratch (allocation-free rule: __device__ globals)
__device__ float g_s[BHW];    // channel sum, 1 MiB
__device__ float g_x1[BHW];   // conv result, 1 MiB

// ---------------------------------------------------------------------------
// Kernel 1: s[b,hw] = sum_c x[b,c,hw]   (float4 over hw)
// grid covers B*HW/4 = 65536 float4 outputs
// ---------------------------------------------------------------------------
__global__ void __launch_bounds__(128) reduce_c_kernel(const float4* __restrict__ x,
                                                       float4* __restrict__ s) {
    int i = blockIdx.x * blockDim.x + threadIdx.x;      // 0 .. 65535
    int b   = i >> 12;                                  // HW/4 = 4096
    int hw4 = i & 4095;
    const float4* p = x + (size_t)b * (CHW / 4) + hw4;

    float4 acc = make_float4(0.f, 0.f, 0.f, 0.f);
#pragma unroll 8
    for (int c = 0; c < Cn; ++c) {
        float4 v = p[(size_t)c * (HW / 4)];
        acc.x += v.x; acc.y += v.y; acc.z += v.z; acc.w += v.w;
    }
    s[i] = acc;
}

// ---------------------------------------------------------------------------
// Kernel 2: x1 = conv3x3(s) with zero pad, cross-correlation (XLA semantics)
// one thread per output element, B*HW = 262144 threads. Tiny (~1 MiB traffic).
// ---------------------------------------------------------------------------
__global__ void __launch_bounds__(256) conv3_kernel(const float* __restrict__ s,
                                                    const float* __restrict__ f,
                                                    float* __restrict__ x1) {
    int i = blockIdx.x * blockDim.x + threadIdx.x;      // 0 .. BHW-1
    if (i >= BHW) return;
    int b  = i >> 14;
    int hw = i & (HW - 1);
    int h  = hw >> 7;
    int w  = hw & (Wn - 1);

    const float* sb = s + b * HW;
    float acc = 0.f;
#pragma unroll
    for (int di = 0; di < 3; ++di) {
        int hh = h + di - 1;
        if (hh < 0 || hh >= Hn) continue;
#pragma unroll
        for (int dj = 0; dj < 3; ++dj) {
            int ww = w + dj - 1;
            if (ww < 0 || ww >= Wn) continue;
            acc += sb[hh * Wn + ww] * f[di * 3 + dj];
        }
    }
    x1[i] = acc;
}

// ---------------------------------------------------------------------------
// Kernel 3: out[b,c,hw] = x[b,c,hw] - x1[b,hw]   (float4)
// grid covers TOTAL/4 = 16777216 float4 elements
// ---------------------------------------------------------------------------
__global__ void __launch_bounds__(256) sub_kernel(const float4* __restrict__ x,
                                                  const float4* __restrict__ x1,
                                                  float4* __restrict__ out) {
    int i = blockIdx.x * blockDim.x + threadIdx.x;      // 0 .. 2^24-1
    float4 xv = x[i];
    // b = i >> 20 (CHW/4 = 2^20), hw4 = i & 4095 (HW/4 = 4096)
    float4 bv = x1[((i >> 20) << 12) + (i & 4095)];
    float4 o;
    o.x = xv.x - bv.x;
    o.y = xv.y - bv.y;
    o.z = xv.z - bv.z;
    o.w = xv.w - bv.w;
    out[i] = o;
}

// ---------------------------------------------------------------------------
extern "C" void kernel_launch(void* const* d_in, const int* in_sizes, int n_in,
                              void* d_out, int out_size) {
    const float* x = (const float*)d_in[0];   // (16,256,128,128) fp32
    const float* f = (const float*)d_in[1];   // (3,3) fp32
    float* out = (float*)d_out;

    static float* s_ptr  = nullptr;
    static float* x1_ptr = nullptr;
    if (s_ptr == nullptr) {
        cudaGetSymbolAddress((void**)&s_ptr,  g_s);
        cudaGetSymbolAddress((void**)&x1_ptr, g_x1);
    }

    // K1: channel reduction
    {
        int n4 = BHW / 4;                 // 65536
        int tpb = 128;
        reduce_c_kernel<<<n4 / tpb, tpb>>>((const float4*)x, (float4*)s_ptr);
    }
    // K2: tiny conv
    {
        int tpb = 256;
        conv3_kernel<<<(BHW + tpb - 1) / tpb, tpb>>>(s_ptr, f, x1_ptr);
    }
    // K3: broadcast subtract
    {
        int n4 = TOTAL / 4;               // 16777216
        int tpb = 256;
        sub_kernel<<<n4 / tpb, tpb>>>((const float4*)x, (const float4*)x1_ptr,
                                      (float4*)out);
    }
}